// round 14
// baseline (speedup 1.0000x reference)
#include <cuda_runtime.h>
#include <cuda_bf16.h>
#include <cstdint>
#include <math.h>

#define B_  2
#define T_  2048
#define C_  2048
#define H_  16
#define HD_ 128
#define C3_ 6144
#define M_  (B_*T_)

// ---------------- scratch (no allocations allowed) ----------------
__device__ float g_cos[T_ * 64];
__device__ float g_sin[T_ * 64];
// pre-split bf16 hi/lo operands (GEMM)
__device__ __nv_bfloat16 g_xh[(size_t)M_ * C_],  g_xl[(size_t)M_ * C_];
__device__ __nv_bfloat16 g_wqh[(size_t)C3_ * C_], g_wql[(size_t)C3_ * C_];
__device__ __nv_bfloat16 g_woh[(size_t)C_ * C_],  g_wol[(size_t)C_ * C_];
__device__ __nv_bfloat16 g_atth[(size_t)M_ * C_], g_attl[(size_t)M_ * C_];
// pre-roped pre-split q/k/v, head-major [B,H,T,HD]
#define QKV_HM ((size_t)B_ * H_ * T_ * HD_)
__device__ __nv_bfloat16 g_qh[QKV_HM], g_ql[QKV_HM];
__device__ __nv_bfloat16 g_kh[QKV_HM], g_kl[QKV_HM];
__device__ __nv_bfloat16 g_vh[QKV_HM], g_vl[QKV_HM];

// ================= helpers =================
__device__ __forceinline__ uint32_t smem_u32(const void* p) {
    uint32_t a;
    asm("{ .reg .u64 t; cvta.to.shared.u64 t, %1; cvt.u32.u64 %0, t; }" : "=r"(a) : "l"(p));
    return a;
}
__device__ __forceinline__ void mma_bf16(float* c, const uint32_t* a, const uint32_t* b) {
    asm volatile(
        "mma.sync.aligned.m16n8k16.row.col.f32.bf16.bf16.f32 "
        "{%0,%1,%2,%3}, {%4,%5,%6,%7}, {%8,%9}, {%0,%1,%2,%3};"
        : "+f"(c[0]), "+f"(c[1]), "+f"(c[2]), "+f"(c[3])
        : "r"(a[0]), "r"(a[1]), "r"(a[2]), "r"(a[3]), "r"(b[0]), "r"(b[1]));
}
__device__ __forceinline__ void ldsm_x4(uint32_t* d, uint32_t addr) {
    asm volatile("ldmatrix.sync.aligned.m8n8.x4.shared.b16 {%0,%1,%2,%3}, [%4];"
                 : "=r"(d[0]), "=r"(d[1]), "=r"(d[2]), "=r"(d[3]) : "r"(addr));
}
__device__ __forceinline__ void ldsm_x4_t(uint32_t* d, uint32_t addr) {
    asm volatile("ldmatrix.sync.aligned.m8n8.x4.trans.shared.b16 {%0,%1,%2,%3}, [%4];"
                 : "=r"(d[0]), "=r"(d[1]), "=r"(d[2]), "=r"(d[3]) : "r"(addr));
}
__device__ __forceinline__ uint32_t pack_hi(float x0, float x1) {
    uint32_t u0 = __float_as_uint(x0), u1 = __float_as_uint(x1);
    return (u0 >> 16) | (u1 & 0xFFFF0000u);
}
__device__ __forceinline__ uint32_t pack_lo(float x0, float x1) {
    float h0 = __uint_as_float(__float_as_uint(x0) & 0xFFFF0000u);
    float h1 = __uint_as_float(__float_as_uint(x1) & 0xFFFF0000u);
    __nv_bfloat162 v = __floats2bfloat162_rn(x0 - h0, x1 - h1);
    return *reinterpret_cast<uint32_t*>(&v);
}
#define CP_ASYNC16(dst, src) \
    asm volatile("cp.async.cg.shared.global [%0], [%1], 16;" :: "r"(dst), "l"(src))
#define CP_COMMIT() asm volatile("cp.async.commit_group;" ::: "memory")
#define CP_WAIT(n)  asm volatile("cp.async.wait_group %0;" :: "n"(n) : "memory")

// ---------------- fused prep: RoPE tables + 3 hi/lo splits ----------------
#define ROPE_N (T_ * 64)
#define N4X (M_ * C_ / 4)
#define N4Q (C3_ * C_ / 4)
#define N4O (C_ * C_ / 4)
#define PREP_TOTAL (ROPE_N + N4X + N4Q + N4O)

__global__ void prep_k(const float* __restrict__ x,
                       const float* __restrict__ Wq,
                       const float* __restrict__ Wo) {
    int idx = blockIdx.x * blockDim.x + threadIdx.x;
    if (idx < ROPE_N) {
        int t = idx >> 6, p = idx & 63;
        double theta = exp(-log(10000.0) * exp2((double)p) / 128.0);
        double ang = (double)(t + 1) * theta;
        g_cos[idx] = (float)cos(ang);
        g_sin[idx] = (float)sin(ang);
        return;
    }
    int i = idx - ROPE_N;
    const float* src;
    __nv_bfloat16 *hi, *lo;
    if (i < N4X)            { src = x;  hi = g_xh;  lo = g_xl; }
    else if (i < N4X + N4Q) { i -= N4X; src = Wq; hi = g_wqh; lo = g_wql; }
    else if (i < N4X + N4Q + N4O) { i -= N4X + N4Q; src = Wo; hi = g_woh; lo = g_wol; }
    else return;
    float4 v = ((const float4*)src)[i];
    ((uint2*)hi)[i] = make_uint2(pack_hi(v.x, v.y), pack_hi(v.z, v.w));
    ((uint2*)lo)[i] = make_uint2(pack_lo(v.x, v.y), pack_lo(v.z, v.w));
}

// ===== bf16x3 HMMA GEMM (r9 mainloop): C = A[M,K]*B[N,K]^T + bias =====
// BM=256, BN=128, BK=64, 8 warps in 4x2, warp tile 64x64, 2-stage cp.async.
// qkv_mode=1: epilogue applies bias + RoPE + hi/lo split, writes head-major q/k/v.
#define GROWH 72
#define ATILE_B (256 * GROWH * 2)
#define BTILE_B (128 * GROWH * 2)
#define GB_OFF  (2 * ATILE_B)
#define GSTAGE_B (2 * ATILE_B + 2 * BTILE_B)
#define GEMM_SMEM (2 * GSTAGE_B)
#define EROW 132

__global__ void __launch_bounds__(256, 1)
gemm_bf16x3_k(const __nv_bfloat16* __restrict__ Ah, const __nv_bfloat16* __restrict__ Al,
              const __nv_bfloat16* __restrict__ Bh, const __nv_bfloat16* __restrict__ Bl,
              const float* __restrict__ bias, float* __restrict__ Cm,
              int K, int ldc, int qkv_mode) {
    extern __shared__ char smem[];
    const uint32_t sb = smem_u32(smem);
    const int tid = threadIdx.x;
    const int wid = tid >> 5, lid = tid & 31;
    const int m0 = blockIdx.y * 256, n0 = blockIdx.x * 128;

    const __nv_bfloat16* a_srcs[2] = { Ah + (size_t)m0 * K, Al + (size_t)m0 * K };
    const __nv_bfloat16* b_srcs[2] = { Bh + (size_t)n0 * K, Bl + (size_t)n0 * K };

    const int lrow = tid >> 3;
    const int lk16 = tid & 7;

    const int wm = (wid >> 1) * 64, wn = (wid & 1) * 64;
    const int a_row = (lid & 7) + ((lid >> 3) & 1) * 8;
    const int a_kb  = ((lid >> 4) & 1) * 8;
    const int b_row = (lid & 7) + ((lid >> 4) & 1) * 8;
    const int b_kb  = ((lid >> 3) & 1) * 8;

    const int nch = K / 64;

    auto load_stage = [&](int buf, int ch) {
        const uint32_t stb = sb + (uint32_t)buf * GSTAGE_B;
        const size_t ko = (size_t)ch * 64;
#pragma unroll
        for (int t = 0; t < 2; t++) {
#pragma unroll
            for (int j = 0; j < 8; j++) {
                int row = j * 32 + lrow;
                uint32_t dst = stb + (uint32_t)t * ATILE_B + (uint32_t)(row * GROWH + lk16 * 8) * 2;
                CP_ASYNC16(dst, a_srcs[t] + (size_t)row * K + ko + lk16 * 8);
            }
#pragma unroll
            for (int j = 0; j < 4; j++) {
                int row = j * 32 + lrow;
                uint32_t dst = stb + GB_OFF + (uint32_t)t * BTILE_B + (uint32_t)(row * GROWH + lk16 * 8) * 2;
                CP_ASYNC16(dst, b_srcs[t] + (size_t)row * K + ko + lk16 * 8);
            }
        }
        CP_COMMIT();
    };

    float acc[4][8][4];
#pragma unroll
    for (int i = 0; i < 4; i++)
#pragma unroll
        for (int j = 0; j < 8; j++)
#pragma unroll
            for (int c = 0; c < 4; c++) acc[i][j][c] = 0.f;

    load_stage(0, 0);
    if (nch > 1) load_stage(1, 1);

    for (int ch = 0; ch < nch; ch++) {
        if (ch + 1 < nch) CP_WAIT(1); else CP_WAIT(0);
        __syncthreads();
        const uint32_t st = sb + (uint32_t)(ch & 1) * GSTAGE_B;
#pragma unroll
        for (int ks = 0; ks < 4; ks++) {
            uint32_t ah[4][4], al[4][4];
#pragma unroll
            for (int mt = 0; mt < 4; mt++) {
                uint32_t ro = (uint32_t)((wm + mt * 16 + a_row) * GROWH + ks * 16 + a_kb) * 2;
                ldsm_x4(ah[mt], st + 0 * ATILE_B + ro);
                ldsm_x4(al[mt], st + 1 * ATILE_B + ro);
            }
#pragma unroll
            for (int half = 0; half < 2; half++) {
                uint32_t bh[2][4], bl[2][4];
#pragma unroll
                for (int p = 0; p < 2; p++) {
                    int np = half * 2 + p;
                    uint32_t ro = (uint32_t)((wn + np * 16 + b_row) * GROWH + ks * 16 + b_kb) * 2;
                    ldsm_x4(bh[p], st + GB_OFF + 0 * BTILE_B + ro);
                    ldsm_x4(bl[p], st + GB_OFF + 1 * BTILE_B + ro);
                }
#pragma unroll
                for (int mt = 0; mt < 4; mt++)
#pragma unroll
                    for (int p = 0; p < 2; p++) {
                        int nt = half * 4 + p * 2;
                        mma_bf16(acc[mt][nt],     ah[mt], bh[p]);
                        mma_bf16(acc[mt][nt],     ah[mt], bl[p]);
                        mma_bf16(acc[mt][nt],     al[mt], bh[p]);
                        mma_bf16(acc[mt][nt + 1], ah[mt], bh[p] + 2);
                        mma_bf16(acc[mt][nt + 1], ah[mt], bl[p] + 2);
                        mma_bf16(acc[mt][nt + 1], al[mt], bh[p] + 2);
                    }
            }
        }
        __syncthreads();
        if (ch + 2 < nch) load_stage(ch & 1, ch + 2);
    }

    const int cr = lid >> 2, cc = (lid & 3) * 2;

    if (qkv_mode) {
        // ---- epilogue A: acc+bias -> padded fp32 smem tile [256][132] (16B-aligned rows)
        float* smf = (float*)smem;
#pragma unroll
        for (int mt = 0; mt < 4; mt++) {
#pragma unroll
            for (int nt = 0; nt < 8; nt++) {
                int lr0 = wm + mt * 16 + cr;
                int lc = wn + nt * 8 + cc;
                float b0 = bias[n0 + lc], b1 = bias[n0 + lc + 1];
                smf[lr0 * EROW + lc]           = acc[mt][nt][0] + b0;
                smf[lr0 * EROW + lc + 1]       = acc[mt][nt][1] + b1;
                smf[(lr0 + 8) * EROW + lc]     = acc[mt][nt][2] + b0;
                smf[(lr0 + 8) * EROW + lc + 1] = acc[mt][nt][3] + b1;
            }
        }
        __syncthreads();
        // ---- epilogue B: RoPE (q,k) / passthrough (v) + hi/lo split, head-major store
        const int sec = n0 >> 11;             // 0=q, 1=k, 2=v
        const int h = (n0 & 2047) >> 7;       // head (tile == one full head)
        __nv_bfloat16* hi = (sec == 0) ? g_qh : (sec == 1) ? g_kh : g_vh;
        __nv_bfloat16* lo = (sec == 0) ? g_ql : (sec == 1) ? g_kl : g_vl;
        if (sec < 2) {
            const int half = lid >> 4;        // 2 rows per warp-iter
            const int c = (lid & 15) * 4;     // 0..60
#pragma unroll 4
            for (int it = 0; it < 16; it++) {
                int r = wid * 32 + it * 2 + half;
                int m = m0 + r;
                int t = m & (T_ - 1), bb = m >> 11;
                size_t ob = ((size_t)(bb * H_ + h) * T_ + t) * HD_;
                float4 xa = *(float4*)&smf[r * EROW + c];
                float4 xb = *(float4*)&smf[r * EROW + c + 64];
                float4 cs = *(const float4*)(g_cos + t * 64 + c);
                float4 sn = *(const float4*)(g_sin + t * 64 + c);
                float4 ra, rb;
                ra.x = xa.x * cs.x - xb.x * sn.x;  rb.x = xb.x * cs.x + xa.x * sn.x;
                ra.y = xa.y * cs.y - xb.y * sn.y;  rb.y = xb.y * cs.y + xa.y * sn.y;
                ra.z = xa.z * cs.z - xb.z * sn.z;  rb.z = xb.z * cs.z + xa.z * sn.z;
                ra.w = xa.w * cs.w - xb.w * sn.w;  rb.w = xb.w * cs.w + xa.w * sn.w;
                *(uint2*)(hi + ob + c)      = make_uint2(pack_hi(ra.x, ra.y), pack_hi(ra.z, ra.w));
                *(uint2*)(lo + ob + c)      = make_uint2(pack_lo(ra.x, ra.y), pack_lo(ra.z, ra.w));
                *(uint2*)(hi + ob + c + 64) = make_uint2(pack_hi(rb.x, rb.y), pack_hi(rb.z, rb.w));
                *(uint2*)(lo + ob + c + 64) = make_uint2(pack_lo(rb.x, rb.y), pack_lo(rb.z, rb.w));
            }
        } else {
            const int c = lid * 4;            // 0..124
#pragma unroll 4
            for (int it = 0; it < 32; it++) {
                int r = wid * 32 + it;
                int m = m0 + r;
                int t = m & (T_ - 1), bb = m >> 11;
                size_t ob = ((size_t)(bb * H_ + h) * T_ + t) * HD_;
                float4 v = *(float4*)&smf[r * EROW + c];
                *(uint2*)(hi + ob + c) = make_uint2(pack_hi(v.x, v.y), pack_hi(v.z, v.w));
                *(uint2*)(lo + ob + c) = make_uint2(pack_lo(v.x, v.y), pack_lo(v.z, v.w));
            }
        }
        return;
    }

    // ---- plain epilogue (out-projection): bias + fp32 stores
#pragma unroll
    for (int mt = 0; mt < 4; mt++) {
#pragma unroll
        for (int nt = 0; nt < 8; nt++) {
            int gr = m0 + wm + mt * 16 + cr;
            int gc = n0 + wn + nt * 8 + cc;
            float b0 = bias[gc], b1 = bias[gc + 1];
            float* p0 = Cm + (size_t)gr * ldc + gc;
            float* p1 = Cm + (size_t)(gr + 8) * ldc + gc;
            *(float2*)p0 = make_float2(acc[mt][nt][0] + b0, acc[mt][nt][1] + b1);
            *(float2*)p1 = make_float2(acc[mt][nt][2] + b0, acc[mt][nt][3] + b1);
        }
    }
}

// ===== HMMA flash attention (causal, pre-split inputs, cp.async pipelined) =====
#define FROWH 136
#define FQH 0
#define FQL 17408
#define FST0 34816
#define FSTAGE 34816
#define KH_L 0
#define KL_L 8704
#define VH_L 17408
#define VL_L 26112
#define FA2_SMEM ((FST0 + 2 * FSTAGE) * 2)   // 208896 B

__global__ void __launch_bounds__(256, 1)
flash_attn_mma_k() {
    extern __shared__ uint16_t sh[];
    const uint32_t sb = smem_u32(sh);
    const int tid = threadIdx.x, wid = tid >> 5, lane = tid & 31;
    const int qb = (int)gridDim.x - 1 - (int)blockIdx.x;  // big work first
    const int h = blockIdx.y, b = blockIdx.z;
    const int q0 = qb * 128;
    const float scale = 0.08838834764831845f;  // 1/sqrt(128)

    const size_t hm = (size_t)(b * H_ + h) * T_;

    {
        const int r = tid >> 1;
        const int cb = (tid & 1) * 8;
        const __nv_bfloat16* qh = g_qh + (hm + q0 + r) * HD_;
        const __nv_bfloat16* ql = g_ql + (hm + q0 + r) * HD_;
#pragma unroll
        for (int j = 0; j < 8; j++) {
            CP_ASYNC16(sb + (uint32_t)(FQH + r * FROWH + (cb + j) * 8) * 2, qh + (cb + j) * 8);
            CP_ASYNC16(sb + (uint32_t)(FQL + r * FROWH + (cb + j) * 8) * 2, ql + (cb + j) * 8);
        }
        CP_COMMIT();
    }

    const int r_ld = tid >> 2;
    const int cb_ld = (tid & 3) * 4;

    auto load_kv = [&](int buf, int kt) {
        const size_t ko = (hm + kt * 64 + r_ld) * HD_;
        const __nv_bfloat16* srcs[4] = { g_kh + ko, g_kl + ko, g_vh + ko, g_vl + ko };
        const uint32_t toff[4] = { KH_L, KL_L, VH_L, VL_L };
        const uint32_t stb = (uint32_t)(FST0 + buf * FSTAGE);
#pragma unroll
        for (int t = 0; t < 4; t++) {
#pragma unroll
            for (int j = 0; j < 4; j++) {
                CP_ASYNC16(sb + (stb + toff[t] + (uint32_t)(r_ld * FROWH + (cb_ld + j) * 8)) * 2,
                           srcs[t] + (cb_ld + j) * 8);
            }
        }
        CP_COMMIT();
    };

    const int ktmax = 2 * qb + 1;
    load_kv(0, 0);
    load_kv(1, 1);

    float m_[2] = {-1e30f, -1e30f}, l_[2] = {0.f, 0.f};
    float o_[16][4];
#pragma unroll
    for (int nt = 0; nt < 16; nt++)
#pragma unroll
        for (int c = 0; c < 4; c++) o_[nt][c] = 0.f;

    for (int kt = 0; kt <= ktmax; kt++) {
        if (kt < ktmax) CP_WAIT(1); else CP_WAIT(0);
        __syncthreads();
        const uint32_t stb = sb + (uint32_t)(FST0 + (kt & 1) * FSTAGE) * 2;

        float s[8][4];
#pragma unroll
        for (int nt = 0; nt < 8; nt++)
#pragma unroll
            for (int c = 0; c < 4; c++) s[nt][c] = 0.f;

#pragma unroll
        for (int kk = 0; kk < 8; kk++) {
            uint32_t aqh[4], aql[4];
            const uint32_t ar = sb + (uint32_t)((wid * 16 + (lane & 15)) * FROWH + kk * 16 + (lane >> 4) * 8) * 2;
            ldsm_x4(aqh, ar + FQH * 2);
            ldsm_x4(aql, ar + FQL * 2);
#pragma unroll
            for (int np = 0; np < 4; np++) {
                uint32_t bh[4], bl[4];
                const uint32_t br = stb + (uint32_t)((np * 16 + (lane & 7) + ((lane >> 4) & 1) * 8) * FROWH +
                                                     kk * 16 + ((lane >> 3) & 1) * 8) * 2;
                ldsm_x4(bh, br + KH_L * 2);
                ldsm_x4(bl, br + KL_L * 2);
                mma_bf16(s[2 * np],     aqh, bh);
                mma_bf16(s[2 * np],     aqh, bl);
                mma_bf16(s[2 * np],     aql, bh);
                mma_bf16(s[2 * np + 1], aqh, bh + 2);
                mma_bf16(s[2 * np + 1], aqh, bl + 2);
                mma_bf16(s[2 * np + 1], aql, bh + 2);
            }
        }

        const bool msk = (kt >= 2 * qb);
        const int rbase = q0 + wid * 16 + (lane >> 2);
        const int kbase = kt * 64 + (lane & 3) * 2;
#pragma unroll
        for (int i = 0; i < 2; i++) {
            const int rg = rbase + i * 8;
            float mx = -1e30f;
#pragma unroll
            for (int nt = 0; nt < 8; nt++)
#pragma unroll
                for (int c = 0; c < 2; c++) {
                    float v = s[nt][i * 2 + c] * scale;
                    if (msk && (kbase + nt * 8 + c) > rg) v = -1e30f;
                    s[nt][i * 2 + c] = v;
                    mx = fmaxf(mx, v);
                }
            mx = fmaxf(mx, __shfl_xor_sync(0xffffffffu, mx, 1));
            mx = fmaxf(mx, __shfl_xor_sync(0xffffffffu, mx, 2));
            float mn = fmaxf(m_[i], mx);
            float al = __expf(m_[i] - mn);
            m_[i] = mn;
            float rs = 0.f;
#pragma unroll
            for (int nt = 0; nt < 8; nt++)
#pragma unroll
                for (int c = 0; c < 2; c++) {
                    float p = __expf(s[nt][i * 2 + c] - mn);
                    s[nt][i * 2 + c] = p;
                    rs += p;
                }
            rs += __shfl_xor_sync(0xffffffffu, rs, 1);
            rs += __shfl_xor_sync(0xffffffffu, rs, 2);
            l_[i] = l_[i] * al + rs;
#pragma unroll
            for (int nt = 0; nt < 16; nt++) { o_[nt][i * 2] *= al; o_[nt][i * 2 + 1] *= al; }
        }

#pragma unroll
        for (int kk = 0; kk < 4; kk++) {
            uint32_t ph[4], pl[4];
            ph[0] = pack_hi(s[2 * kk][0], s[2 * kk][1]);
            ph[1] = pack_hi(s[2 * kk][2], s[2 * kk][3]);
            ph[2] = pack_hi(s[2 * kk + 1][0], s[2 * kk + 1][1]);
            ph[3] = pack_hi(s[2 * kk + 1][2], s[2 * kk + 1][3]);
            pl[0] = pack_lo(s[2 * kk][0], s[2 * kk][1]);
            pl[1] = pack_lo(s[2 * kk][2], s[2 * kk][3]);
            pl[2] = pack_lo(s[2 * kk + 1][0], s[2 * kk + 1][1]);
            pl[3] = pack_lo(s[2 * kk + 1][2], s[2 * kk + 1][3]);
#pragma unroll
            for (int np = 0; np < 8; np++) {
                uint32_t vh[4], vl[4];
                const uint32_t vr = stb + (uint32_t)((kk * 16 + (lane & 7) + ((lane >> 3) & 1) * 8) * FROWH +
                                                     np * 16 + ((lane >> 4) & 1) * 8) * 2;
                ldsm_x4_t(vh, vr + VH_L * 2);
                ldsm_x4_t(vl, vr + VL_L * 2);
                mma_bf16(o_[2 * np],     ph, vh);
                mma_bf16(o_[2 * np],     ph, vl);
                mma_bf16(o_[2 * np],     pl, vh);
                mma_bf16(o_[2 * np + 1], ph, vh + 2);
                mma_bf16(o_[2 * np + 1], ph, vl + 2);
                mma_bf16(o_[2 * np + 1], pl, vh + 2);
            }
        }
        __syncthreads();
        if (kt + 2 <= ktmax) load_kv(kt & 1, kt + 2);
    }

    const float inv0 = 1.f / l_[0], inv1 = 1.f / l_[1];
    const int rg0 = b * T_ + q0 + wid * 16 + (lane >> 2);
    const size_t colb = (size_t)h * HD_ + (lane & 3) * 2;
#pragma unroll
    for (int nt = 0; nt < 16; nt++) {
        float a0 = o_[nt][0] * inv0, a1 = o_[nt][1] * inv0;
        float b0 = o_[nt][2] * inv1, b1 = o_[nt][3] * inv1;
        size_t off0 = (size_t)rg0 * C_ + colb + nt * 8;
        size_t off1 = (size_t)(rg0 + 8) * C_ + colb + nt * 8;
        *(uint32_t*)&g_atth[off0] = pack_hi(a0, a1);
        *(uint32_t*)&g_attl[off0] = pack_lo(a0, a1);
        *(uint32_t*)&g_atth[off1] = pack_hi(b0, b1);
        *(uint32_t*)&g_attl[off1] = pack_lo(b0, b1);
    }
}

// ---------------- launch ----------------
extern "C" void kernel_launch(void* const* d_in, const int* in_sizes, int n_in,
                              void* d_out, int out_size) {
    const float* x    = (const float*)d_in[0];
    const float* Wqkv = (const float*)d_in[1];
    const float* bqkv = (const float*)d_in[2];
    const float* Wo   = (const float*)d_in[3];
    const float* bo   = (const float*)d_in[4];
    float* out = (float*)d_out;

    void *xh, *xl, *wqh, *wql, *woh, *wol, *ath, *atl;
    cudaGetSymbolAddress(&xh, g_xh);   cudaGetSymbolAddress(&xl, g_xl);
    cudaGetSymbolAddress(&wqh, g_wqh); cudaGetSymbolAddress(&wql, g_wql);
    cudaGetSymbolAddress(&woh, g_woh); cudaGetSymbolAddress(&wol, g_wol);
    cudaGetSymbolAddress(&ath, g_atth); cudaGetSymbolAddress(&atl, g_attl);

    cudaFuncSetAttribute(gemm_bf16x3_k, cudaFuncAttributeMaxDynamicSharedMemorySize, GEMM_SMEM);
    cudaFuncSetAttribute(flash_attn_mma_k, cudaFuncAttributeMaxDynamicSharedMemorySize, FA2_SMEM);

    // 1. fused prep: RoPE tables + x/Wqkv/Wo hi-lo splits
    prep_k<<<(PREP_TOTAL + 255) / 256, 256>>>(x, Wqkv, Wo);
    // 2. QKV projection with fused bias+RoPE+split epilogue -> head-major q/k/v
    gemm_bf16x3_k<<<dim3(C3_ / 128, M_ / 256), 256, GEMM_SMEM>>>(
        (const __nv_bfloat16*)xh, (const __nv_bfloat16*)xl,
        (const __nv_bfloat16*)wqh, (const __nv_bfloat16*)wql, bqkv, nullptr, C_, C3_, 1);
    // 3. causal flash attention (pre-split inputs, cp.async pipelined)
    flash_attn_mma_k<<<dim3(T_ / 128, H_, B_), 256, FA2_SMEM>>>();
    // 4. output projection (plain epilogue) -> d_out
    gemm_bf16x3_k<<<dim3(C_ / 128, M_ / 256), 256, GEMM_SMEM>>>(
        (const __nv_bfloat16*)ath, (const __nv_bfloat16*)atl,
        (const __nv_bfloat16*)woh, (const __nv_bfloat16*)wol, bo, out, C_, C_, 0);
}

// round 17
// speedup vs baseline: 1.5548x; 1.5548x over previous
#include <cuda_runtime.h>
#include <cuda_bf16.h>
#include <cstdint>
#include <math.h>

#define B_  2
#define T_  2048
#define C_  2048
#define H_  16
#define HD_ 128
#define C3_ 6144
#define M_  (B_*T_)

// ---------------- scratch (no allocations allowed) ----------------
__device__ float g_qkv[(size_t)B_ * T_ * C3_];   // [B,T,3C] fp32
__device__ float g_cos[T_ * 64];
__device__ float g_sin[T_ * 64];
__device__ __nv_bfloat16 g_xh[(size_t)M_ * C_],  g_xl[(size_t)M_ * C_];
__device__ __nv_bfloat16 g_wqh[(size_t)C3_ * C_], g_wql[(size_t)C3_ * C_];
__device__ __nv_bfloat16 g_woh[(size_t)C_ * C_],  g_wol[(size_t)C_ * C_];
__device__ __nv_bfloat16 g_atth[(size_t)M_ * C_], g_attl[(size_t)M_ * C_];
#define QKV_HM ((size_t)B_ * H_ * T_ * HD_)
__device__ __nv_bfloat16 g_qh[QKV_HM], g_ql[QKV_HM];
__device__ __nv_bfloat16 g_kh[QKV_HM], g_kl[QKV_HM];
__device__ __nv_bfloat16 g_vh[QKV_HM], g_vl[QKV_HM];

// ================= helpers =================
__device__ __forceinline__ uint32_t smem_u32(const void* p) {
    uint32_t a;
    asm("{ .reg .u64 t; cvta.to.shared.u64 t, %1; cvt.u32.u64 %0, t; }" : "=r"(a) : "l"(p));
    return a;
}
__device__ __forceinline__ void mma_bf16(float* c, const uint32_t* a, const uint32_t* b) {
    asm volatile(
        "mma.sync.aligned.m16n8k16.row.col.f32.bf16.bf16.f32 "
        "{%0,%1,%2,%3}, {%4,%5,%6,%7}, {%8,%9}, {%0,%1,%2,%3};"
        : "+f"(c[0]), "+f"(c[1]), "+f"(c[2]), "+f"(c[3])
        : "r"(a[0]), "r"(a[1]), "r"(a[2]), "r"(a[3]), "r"(b[0]), "r"(b[1]));
}
__device__ __forceinline__ void ldsm_x4(uint32_t* d, uint32_t addr) {
    asm volatile("ldmatrix.sync.aligned.m8n8.x4.shared.b16 {%0,%1,%2,%3}, [%4];"
                 : "=r"(d[0]), "=r"(d[1]), "=r"(d[2]), "=r"(d[3]) : "r"(addr));
}
__device__ __forceinline__ void ldsm_x4_t(uint32_t* d, uint32_t addr) {
    asm volatile("ldmatrix.sync.aligned.m8n8.x4.trans.shared.b16 {%0,%1,%2,%3}, [%4];"
                 : "=r"(d[0]), "=r"(d[1]), "=r"(d[2]), "=r"(d[3]) : "r"(addr));
}
__device__ __forceinline__ uint32_t pack_hi(float x0, float x1) {
    uint32_t u0 = __float_as_uint(x0), u1 = __float_as_uint(x1);
    return (u0 >> 16) | (u1 & 0xFFFF0000u);
}
__device__ __forceinline__ uint32_t pack_lo(float x0, float x1) {
    float h0 = __uint_as_float(__float_as_uint(x0) & 0xFFFF0000u);
    float h1 = __uint_as_float(__float_as_uint(x1) & 0xFFFF0000u);
    __nv_bfloat162 v = __floats2bfloat162_rn(x0 - h0, x1 - h1);
    return *reinterpret_cast<uint32_t*>(&v);
}
#define CP_ASYNC16(dst, src) \
    asm volatile("cp.async.cg.shared.global [%0], [%1], 16;" :: "r"(dst), "l"(src))
#define CP_COMMIT() asm volatile("cp.async.commit_group;" ::: "memory")
#define CP_WAIT(n)  asm volatile("cp.async.wait_group %0;" :: "n"(n) : "memory")

// ---------------- fused prep: RoPE tables + 3 hi/lo splits ----------------
#define ROPE_N (T_ * 64)
#define N4X (M_ * C_ / 4)
#define N4Q (C3_ * C_ / 4)
#define N4O (C_ * C_ / 4)
#define PREP_TOTAL (ROPE_N + N4X + N4Q + N4O)

__global__ void prep_k(const float* __restrict__ x,
                       const float* __restrict__ Wq,
                       const float* __restrict__ Wo) {
    int idx = blockIdx.x * blockDim.x + threadIdx.x;
    if (idx < ROPE_N) {
        int t = idx >> 6, p = idx & 63;
        double theta = exp(-log(10000.0) * exp2((double)p) / 128.0);
        double ang = (double)(t + 1) * theta;
        g_cos[idx] = (float)cos(ang);
        g_sin[idx] = (float)sin(ang);
        return;
    }
    int i = idx - ROPE_N;
    const float* src;
    __nv_bfloat16 *hi, *lo;
    if (i < N4X)            { src = x;  hi = g_xh;  lo = g_xl; }
    else if (i < N4X + N4Q) { i -= N4X; src = Wq; hi = g_wqh; lo = g_wql; }
    else if (i < N4X + N4Q + N4O) { i -= N4X + N4Q; src = Wo; hi = g_woh; lo = g_wol; }
    else return;
    float4 v = ((const float4*)src)[i];
    ((uint2*)hi)[i] = make_uint2(pack_hi(v.x, v.y), pack_hi(v.z, v.w));
    ((uint2*)lo)[i] = make_uint2(pack_lo(v.x, v.y), pack_lo(v.z, v.w));
}

// ---------------- rope + split q,k,v into head-major bf16 hi/lo ----------------
#define RS_N (B_ * T_ * H_ * 16)
__global__ void ropesplit_k() {
    int idx = blockIdx.x * blockDim.x + threadIdx.x;
    if (idx >= RS_N) return;
    const int c = (idx & 15) * 4;
    const int h = (idx >> 4) & (H_ - 1);
    const int t = (idx >> 8) & (T_ - 1);
    const int b = idx >> 19;
    const float* base = g_qkv + (size_t)(b * T_ + t) * C3_ + h * HD_;
    float4 cs = *(const float4*)(g_cos + t * 64 + c);
    float4 sn = *(const float4*)(g_sin + t * 64 + c);
    const size_t ob = ((size_t)(b * H_ + h) * T_ + t) * HD_ + c;

#pragma unroll
    for (int sec = 0; sec < 2; sec++) {
        const float* p = base + sec * C_;
        __nv_bfloat16* hi = sec ? g_kh : g_qh;
        __nv_bfloat16* lo = sec ? g_kl : g_ql;
        float4 xa = *(const float4*)(p + c);
        float4 xb = *(const float4*)(p + c + 64);
        float4 ra, rb;
        ra.x = xa.x * cs.x - xb.x * sn.x;  rb.x = xb.x * cs.x + xa.x * sn.x;
        ra.y = xa.y * cs.y - xb.y * sn.y;  rb.y = xb.y * cs.y + xa.y * sn.y;
        ra.z = xa.z * cs.z - xb.z * sn.z;  rb.z = xb.z * cs.z + xa.z * sn.z;
        ra.w = xa.w * cs.w - xb.w * sn.w;  rb.w = xb.w * cs.w + xa.w * sn.w;
        *(uint2*)(hi + ob)      = make_uint2(pack_hi(ra.x, ra.y), pack_hi(ra.z, ra.w));
        *(uint2*)(lo + ob)      = make_uint2(pack_lo(ra.x, ra.y), pack_lo(ra.z, ra.w));
        *(uint2*)(hi + ob + 64) = make_uint2(pack_hi(rb.x, rb.y), pack_hi(rb.z, rb.w));
        *(uint2*)(lo + ob + 64) = make_uint2(pack_lo(rb.x, rb.y), pack_lo(rb.z, rb.w));
    }
    {
        const float* p = base + 2 * C_;
        float4 va = *(const float4*)(p + c);
        float4 vb = *(const float4*)(p + c + 64);
        *(uint2*)(g_vh + ob)      = make_uint2(pack_hi(va.x, va.y), pack_hi(va.z, va.w));
        *(uint2*)(g_vl + ob)      = make_uint2(pack_lo(va.x, va.y), pack_lo(va.z, va.w));
        *(uint2*)(g_vh + ob + 64) = make_uint2(pack_hi(vb.x, vb.y), pack_hi(vb.z, vb.w));
        *(uint2*)(g_vl + ob + 64) = make_uint2(pack_lo(vb.x, vb.y), pack_lo(vb.z, vb.w));
    }
}

// ===== bf16x3 HMMA GEMM (r9 config — measured best): C = A[M,K]*B[N,K]^T + bias =====
#define GROWH 72
#define ATILE_B (256 * GROWH * 2)
#define BTILE_B (128 * GROWH * 2)
#define GB_OFF  (2 * ATILE_B)
#define GSTAGE_B (2 * ATILE_B + 2 * BTILE_B)
#define GEMM_SMEM (2 * GSTAGE_B)

__global__ void __launch_bounds__(256, 1)
gemm_bf16x3_k(const __nv_bfloat16* __restrict__ Ah, const __nv_bfloat16* __restrict__ Al,
              const __nv_bfloat16* __restrict__ Bh, const __nv_bfloat16* __restrict__ Bl,
              const float* __restrict__ bias, float* __restrict__ Cm,
              int K, int ldc) {
    extern __shared__ char smem[];
    const uint32_t sb = smem_u32(smem);
    const int tid = threadIdx.x;
    const int wid = tid >> 5, lid = tid & 31;
    const int m0 = blockIdx.y * 256, n0 = blockIdx.x * 128;

    const __nv_bfloat16* a_srcs[2] = { Ah + (size_t)m0 * K, Al + (size_t)m0 * K };
    const __nv_bfloat16* b_srcs[2] = { Bh + (size_t)n0 * K, Bl + (size_t)n0 * K };

    const int lrow = tid >> 3;
    const int lk16 = tid & 7;

    const int wm = (wid >> 1) * 64, wn = (wid & 1) * 64;
    const int a_row = (lid & 7) + ((lid >> 3) & 1) * 8;
    const int a_kb  = ((lid >> 4) & 1) * 8;
    const int b_row = (lid & 7) + ((lid >> 4) & 1) * 8;
    const int b_kb  = ((lid >> 3) & 1) * 8;

    const int nch = K / 64;

    auto load_stage = [&](int buf, int ch) {
        const uint32_t stb = sb + (uint32_t)buf * GSTAGE_B;
        const size_t ko = (size_t)ch * 64;
#pragma unroll
        for (int t = 0; t < 2; t++) {
#pragma unroll
            for (int j = 0; j < 8; j++) {
                int row = j * 32 + lrow;
                uint32_t dst = stb + (uint32_t)t * ATILE_B + (uint32_t)(row * GROWH + lk16 * 8) * 2;
                CP_ASYNC16(dst, a_srcs[t] + (size_t)row * K + ko + lk16 * 8);
            }
#pragma unroll
            for (int j = 0; j < 4; j++) {
                int row = j * 32 + lrow;
                uint32_t dst = stb + GB_OFF + (uint32_t)t * BTILE_B + (uint32_t)(row * GROWH + lk16 * 8) * 2;
                CP_ASYNC16(dst, b_srcs[t] + (size_t)row * K + ko + lk16 * 8);
            }
        }
        CP_COMMIT();
    };

    float acc[4][8][4];
#pragma unroll
    for (int i = 0; i < 4; i++)
#pragma unroll
        for (int j = 0; j < 8; j++)
#pragma unroll
            for (int c = 0; c < 4; c++) acc[i][j][c] = 0.f;

    load_stage(0, 0);
    if (nch > 1) load_stage(1, 1);

    for (int ch = 0; ch < nch; ch++) {
        if (ch + 1 < nch) CP_WAIT(1); else CP_WAIT(0);
        __syncthreads();
        const uint32_t st = sb + (uint32_t)(ch & 1) * GSTAGE_B;
#pragma unroll
        for (int ks = 0; ks < 4; ks++) {
            uint32_t ah[4][4], al[4][4];
#pragma unroll
            for (int mt = 0; mt < 4; mt++) {
                uint32_t ro = (uint32_t)((wm + mt * 16 + a_row) * GROWH + ks * 16 + a_kb) * 2;
                ldsm_x4(ah[mt], st + 0 * ATILE_B + ro);
                ldsm_x4(al[mt], st + 1 * ATILE_B + ro);
            }
#pragma unroll
            for (int half = 0; half < 2; half++) {
                uint32_t bh[2][4], bl[2][4];
#pragma unroll
                for (int p = 0; p < 2; p++) {
                    int np = half * 2 + p;
                    uint32_t ro = (uint32_t)((wn + np * 16 + b_row) * GROWH + ks * 16 + b_kb) * 2;
                    ldsm_x4(bh[p], st + GB_OFF + 0 * BTILE_B + ro);
                    ldsm_x4(bl[p], st + GB_OFF + 1 * BTILE_B + ro);
                }
#pragma unroll
                for (int mt = 0; mt < 4; mt++)
#pragma unroll
                    for (int p = 0; p < 2; p++) {
                        int nt = half * 4 + p * 2;
                        mma_bf16(acc[mt][nt],     ah[mt], bh[p]);
                        mma_bf16(acc[mt][nt],     ah[mt], bl[p]);
                        mma_bf16(acc[mt][nt],     al[mt], bh[p]);
                        mma_bf16(acc[mt][nt + 1], ah[mt], bh[p] + 2);
                        mma_bf16(acc[mt][nt + 1], ah[mt], bl[p] + 2);
                        mma_bf16(acc[mt][nt + 1], al[mt], bh[p] + 2);
                    }
            }
        }
        __syncthreads();
        if (ch + 2 < nch) load_stage(ch & 1, ch + 2);
    }

    const int cr = lid >> 2, cc = (lid & 3) * 2;
#pragma unroll
    for (int mt = 0; mt < 4; mt++) {
#pragma unroll
        for (int nt = 0; nt < 8; nt++) {
            int gr = m0 + wm + mt * 16 + cr;
            int gc = n0 + wn + nt * 8 + cc;
            float b0 = bias[gc], b1 = bias[gc + 1];
            float* p0 = Cm + (size_t)gr * ldc + gc;
            float* p1 = Cm + (size_t)(gr + 8) * ldc + gc;
            *(float2*)p0 = make_float2(acc[mt][nt][0] + b0, acc[mt][nt][1] + b1);
            *(float2*)p1 = make_float2(acc[mt][nt][2] + b0, acc[mt][nt][3] + b1);
        }
    }
}

// ===== HMMA flash attention (causal, pre-split inputs, S/softmax software pipeline) =====
#define FROWH 136
#define FQH 0
#define FQL 17408
#define FST0 34816
#define FSTAGE 34816
#define KH_L 0
#define KL_L 8704
#define VH_L 17408
#define VL_L 26112
#define FA2_SMEM ((FST0 + 2 * FSTAGE) * 2)   // 208896 B

__global__ void __launch_bounds__(256, 1)
flash_attn_mma_k() {
    extern __shared__ uint16_t sh[];
    const uint32_t sb = smem_u32(sh);
    const int tid = threadIdx.x, wid = tid >> 5, lane = tid & 31;
    const int qb = (int)gridDim.x - 1 - (int)blockIdx.x;  // big work first
    const int h = blockIdx.y, b = blockIdx.z;
    const int q0 = qb * 128;
    const float scale = 0.08838834764831845f;  // 1/sqrt(128)

    const size_t hm = (size_t)(b * H_ + h) * T_;

    // ---- Q cp.async (group)
    {
        const int r = tid >> 1;
        const int cb = (tid & 1) * 8;
        const __nv_bfloat16* qh = g_qh + (hm + q0 + r) * HD_;
        const __nv_bfloat16* ql = g_ql + (hm + q0 + r) * HD_;
#pragma unroll
        for (int j = 0; j < 8; j++) {
            CP_ASYNC16(sb + (uint32_t)(FQH + r * FROWH + (cb + j) * 8) * 2, qh + (cb + j) * 8);
            CP_ASYNC16(sb + (uint32_t)(FQL + r * FROWH + (cb + j) * 8) * 2, ql + (cb + j) * 8);
        }
        CP_COMMIT();
    }

    const int r_ld = tid >> 2;
    const int cb_ld = (tid & 3) * 4;

    auto load_K = [&](int buf, int kt) {
        const size_t ko = (hm + kt * 64 + r_ld) * HD_;
        const uint32_t stb = (uint32_t)(FST0 + buf * FSTAGE);
#pragma unroll
        for (int j = 0; j < 4; j++) {
            CP_ASYNC16(sb + (stb + KH_L + (uint32_t)(r_ld * FROWH + (cb_ld + j) * 8)) * 2, g_kh + ko + (cb_ld + j) * 8);
            CP_ASYNC16(sb + (stb + KL_L + (uint32_t)(r_ld * FROWH + (cb_ld + j) * 8)) * 2, g_kl + ko + (cb_ld + j) * 8);
        }
        CP_COMMIT();
    };
    auto load_V = [&](int buf, int kt) {
        const size_t ko = (hm + kt * 64 + r_ld) * HD_;
        const uint32_t stb = (uint32_t)(FST0 + buf * FSTAGE);
#pragma unroll
        for (int j = 0; j < 4; j++) {
            CP_ASYNC16(sb + (stb + VH_L + (uint32_t)(r_ld * FROWH + (cb_ld + j) * 8)) * 2, g_vh + ko + (cb_ld + j) * 8);
            CP_ASYNC16(sb + (stb + VL_L + (uint32_t)(r_ld * FROWH + (cb_ld + j) * 8)) * 2, g_vl + ko + (cb_ld + j) * 8);
        }
        CP_COMMIT();
    };

    const int ktmax = 2 * qb + 1;           // always odd -> even tile count
    // prologue: K0,V0,K1,V1
    load_K(0, 0); load_V(0, 0);
    load_K(1, 1); load_V(1, 1);

    float m_[2] = {-1e30f, -1e30f}, l_[2] = {0.f, 0.f};
    float o_[16][4];
#pragma unroll
    for (int nt = 0; nt < 16; nt++)
#pragma unroll
        for (int c = 0; c < 4; c++) o_[nt][c] = 0.f;

    // compute S tile into s from stage (kt&1)
    auto compute_S = [&](float (&s)[8][4], int kt) {
#pragma unroll
        for (int nt = 0; nt < 8; nt++)
#pragma unroll
            for (int c = 0; c < 4; c++) s[nt][c] = 0.f;
        const uint32_t stb = sb + (uint32_t)(FST0 + (kt & 1) * FSTAGE) * 2;
#pragma unroll
        for (int kk = 0; kk < 8; kk++) {
            uint32_t aqh[4], aql[4];
            const uint32_t ar = sb + (uint32_t)((wid * 16 + (lane & 15)) * FROWH + kk * 16 + (lane >> 4) * 8) * 2;
            ldsm_x4(aqh, ar + FQH * 2);
            ldsm_x4(aql, ar + FQL * 2);
#pragma unroll
            for (int np = 0; np < 4; np++) {
                uint32_t bh[4], bl[4];
                const uint32_t br = stb + (uint32_t)((np * 16 + (lane & 7) + ((lane >> 4) & 1) * 8) * FROWH +
                                                     kk * 16 + ((lane >> 3) & 1) * 8) * 2;
                ldsm_x4(bh, br + KH_L * 2);
                ldsm_x4(bl, br + KL_L * 2);
                mma_bf16(s[2 * np],     aqh, bh);
                mma_bf16(s[2 * np],     aqh, bl);
                mma_bf16(s[2 * np],     aql, bh);
                mma_bf16(s[2 * np + 1], aqh, bh + 2);
                mma_bf16(s[2 * np + 1], aqh, bl + 2);
                mma_bf16(s[2 * np + 1], aql, bh + 2);
            }
        }
    };

    // softmax + PV for tile kt using scur; also prefetch S(kt+1) into snxt first
    auto process = [&](float (&scur)[8][4], float (&snxt)[8][4], int kt) {
        if (kt < ktmax) {
            CP_WAIT(1);                   // drains V(kt), K(kt+1); leaves V(kt+1) in flight
            __syncthreads();
            compute_S(snxt, kt + 1);      // tensor pipe busy with next tile...
            if (kt + 2 <= ktmax) load_K(kt & 1, kt + 2);   // K stage kt&1 free (S(kt) done pre-barrier)
        } else {
            CP_WAIT(0);                   // last tile: ensure V(ktmax) landed
            __syncthreads();
        }

        // ---- softmax(kt) (overlaps in-flight S(kt+1) mmas)
        const bool msk = (kt >= 2 * qb);
        const int rbase = q0 + wid * 16 + (lane >> 2);
        const int kbase = kt * 64 + (lane & 3) * 2;
#pragma unroll
        for (int i = 0; i < 2; i++) {
            const int rg = rbase + i * 8;
            float mx = -1e30f;
#pragma unroll
            for (int nt = 0; nt < 8; nt++)
#pragma unroll
                for (int c = 0; c < 2; c++) {
                    float v = scur[nt][i * 2 + c] * scale;
                    if (msk && (kbase + nt * 8 + c) > rg) v = -1e30f;
                    scur[nt][i * 2 + c] = v;
                    mx = fmaxf(mx, v);
                }
            mx = fmaxf(mx, __shfl_xor_sync(0xffffffffu, mx, 1));
            mx = fmaxf(mx, __shfl_xor_sync(0xffffffffu, mx, 2));
            float mn = fmaxf(m_[i], mx);
            float al = __expf(m_[i] - mn);
            m_[i] = mn;
            float rs = 0.f;
#pragma unroll
            for (int nt = 0; nt < 8; nt++)
#pragma unroll
                for (int c = 0; c < 2; c++) {
                    float p = __expf(scur[nt][i * 2 + c] - mn);
                    scur[nt][i * 2 + c] = p;
                    rs += p;
                }
            rs += __shfl_xor_sync(0xffffffffu, rs, 1);
            rs += __shfl_xor_sync(0xffffffffu, rs, 2);
            l_[i] = l_[i] * al + rs;
#pragma unroll
            for (int nt = 0; nt < 16; nt++) { o_[nt][i * 2] *= al; o_[nt][i * 2 + 1] *= al; }
        }

        // ---- O += P V
        const uint32_t stb = sb + (uint32_t)(FST0 + (kt & 1) * FSTAGE) * 2;
#pragma unroll
        for (int kk = 0; kk < 4; kk++) {
            uint32_t ph[4], pl[4];
            ph[0] = pack_hi(scur[2 * kk][0], scur[2 * kk][1]);
            ph[1] = pack_hi(scur[2 * kk][2], scur[2 * kk][3]);
            ph[2] = pack_hi(scur[2 * kk + 1][0], scur[2 * kk + 1][1]);
            ph[3] = pack_hi(scur[2 * kk + 1][2], scur[2 * kk + 1][3]);
            pl[0] = pack_lo(scur[2 * kk][0], scur[2 * kk][1]);
            pl[1] = pack_lo(scur[2 * kk][2], scur[2 * kk][3]);
            pl[2] = pack_lo(scur[2 * kk + 1][0], scur[2 * kk + 1][1]);
            pl[3] = pack_lo(scur[2 * kk + 1][2], scur[2 * kk + 1][3]);
#pragma unroll
            for (int np = 0; np < 8; np++) {
                uint32_t vh[4], vl[4];
                const uint32_t vr = stb + (uint32_t)((kk * 16 + (lane & 7) + ((lane >> 3) & 1) * 8) * FROWH +
                                                     np * 16 + ((lane >> 4) & 1) * 8) * 2;
                ldsm_x4_t(vh, vr + VH_L * 2);
                ldsm_x4_t(vl, vr + VL_L * 2);
                mma_bf16(o_[2 * np],     ph, vh);
                mma_bf16(o_[2 * np],     ph, vl);
                mma_bf16(o_[2 * np],     pl, vh);
                mma_bf16(o_[2 * np + 1], ph, vh + 2);
                mma_bf16(o_[2 * np + 1], ph, vl + 2);
                mma_bf16(o_[2 * np + 1], pl, vh + 2);
            }
        }
        __syncthreads();
        if (kt + 2 <= ktmax) load_V(kt & 1, kt + 2);
    };

    // prologue wait: Q, K0, V0 done; K1/V1 may be in flight
    CP_WAIT(2);
    __syncthreads();

    float sA[8][4], sB[8][4];
    compute_S(sA, 0);
    for (int kt = 0; kt < ktmax; kt += 2) {
        process(sA, sB, kt);
        process(sB, sA, kt + 1);
    }

    // ---- normalize + store bf16 hi/lo to g_atth/g_attl [B,T,C]
    const float inv0 = 1.f / l_[0], inv1 = 1.f / l_[1];
    const int rg0 = b * T_ + q0 + wid * 16 + (lane >> 2);
    const size_t colb = (size_t)h * HD_ + (lane & 3) * 2;
#pragma unroll
    for (int nt = 0; nt < 16; nt++) {
        float a0 = o_[nt][0] * inv0, a1 = o_[nt][1] * inv0;
        float b0 = o_[nt][2] * inv1, b1 = o_[nt][3] * inv1;
        size_t off0 = (size_t)rg0 * C_ + colb + nt * 8;
        size_t off1 = (size_t)(rg0 + 8) * C_ + colb + nt * 8;
        *(uint32_t*)&g_atth[off0] = pack_hi(a0, a1);
        *(uint32_t*)&g_attl[off0] = pack_lo(a0, a1);
        *(uint32_t*)&g_atth[off1] = pack_hi(b0, b1);
        *(uint32_t*)&g_attl[off1] = pack_lo(b0, b1);
    }
}

// ---------------- launch ----------------
extern "C" void kernel_launch(void* const* d_in, const int* in_sizes, int n_in,
                              void* d_out, int out_size) {
    const float* x    = (const float*)d_in[0];
    const float* Wqkv = (const float*)d_in[1];
    const float* bqkv = (const float*)d_in[2];
    const float* Wo   = (const float*)d_in[3];
    const float* bo   = (const float*)d_in[4];
    float* out = (float*)d_out;

    void* qkv_p = nullptr; cudaGetSymbolAddress(&qkv_p, g_qkv);
    void *xh, *xl, *wqh, *wql, *woh, *wol, *ath, *atl;
    cudaGetSymbolAddress(&xh, g_xh);   cudaGetSymbolAddress(&xl, g_xl);
    cudaGetSymbolAddress(&wqh, g_wqh); cudaGetSymbolAddress(&wql, g_wql);
    cudaGetSymbolAddress(&woh, g_woh); cudaGetSymbolAddress(&wol, g_wol);
    cudaGetSymbolAddress(&ath, g_atth); cudaGetSymbolAddress(&atl, g_attl);

    cudaFuncSetAttribute(gemm_bf16x3_k, cudaFuncAttributeMaxDynamicSharedMemorySize, GEMM_SMEM);
    cudaFuncSetAttribute(flash_attn_mma_k, cudaFuncAttributeMaxDynamicSharedMemorySize, FA2_SMEM);

    // 1. fused prep
    prep_k<<<(PREP_TOTAL + 255) / 256, 256>>>(x, Wqkv, Wo);
    // 2. QKV projection (r9 GEMM config)
    gemm_bf16x3_k<<<dim3(C3_ / 128, M_ / 256), 256, GEMM_SMEM>>>(
        (const __nv_bfloat16*)xh, (const __nv_bfloat16*)xl,
        (const __nv_bfloat16*)wqh, (const __nv_bfloat16*)wql, bqkv, (float*)qkv_p, C_, C3_);
    // 3. rope+split q,k,v to head-major bf16 hi/lo
    ropesplit_k<<<(RS_N + 255) / 256, 256>>>();
    // 4. causal flash attention (software-pipelined S/softmax overlap)
    flash_attn_mma_k<<<dim3(T_ / 128, H_, B_), 256, FA2_SMEM>>>();
    // 5. output projection
    gemm_bf16x3_k<<<dim3(C_ / 128, M_ / 256), 256, GEMM_SMEM>>>(
        (const __nv_bfloat16*)ath, (const __nv_bfloat16*)atl,
        (const __nv_bfloat16*)woh, (const __nv_bfloat16*)wol, bo, out, C_, C_);
}